// round 4
// baseline (speedup 1.0000x reference)
#include <cuda_runtime.h>
#include <math.h>

// Shapes (static per reference): x, x_r : (1, 3, 32, 512, 512) float32
// size = 64 -> hc = wc = 32 ; patches per frame = 16 x 16 = 256 ; t = 32
// patch mean = sum(|x - x_r|) / (2 * 3072)   [c=3, 32x32 spatial]
// out = log( mean_t( max_patches ) )

#define T_DIM 32
#define NH 16
#define NW 16
#define NPATCH (T_DIM * NH * NW)        // 8192
#define HW 512
#define TSTRIDE (512u * 512u)           // per-t stride in floats
#define CSTRIDE (32u * 512u * 512u)     // per-channel stride in floats

__device__ float g_patch_sum[NPATCH];

__global__ __launch_bounds__(256, 8)
void patch_sum_kernel(const float* __restrict__ x, const float* __restrict__ xr) {
    const int p  = blockIdx.x;          // t*256 + ph*16 + pw
    const int t  = p >> 8;
    const int ph = (p >> 4) & 15;
    const int pw = p & 15;

    const size_t base = (size_t)t * TSTRIDE + (size_t)ph * 32 * HW + (size_t)pw * 32;

    float acc = 0.0f;
    // 3072 floats per tensor = 768 float4 units; 256 threads -> 3 iterations.
    // Linear unit e: c = e/256, row = (e%256)/8, col4 = e%8
    #pragma unroll
    for (int k = 0; k < 3; ++k) {
        const int e   = threadIdx.x + k * 256;
        const int c   = e >> 8;
        const int rem = e & 255;
        const int row = rem >> 3;
        const int col = (rem & 7) << 2;
        const size_t idx = base + (size_t)c * CSTRIDE + (size_t)row * HW + col;
        const float4 a = *reinterpret_cast<const float4*>(x  + idx);
        const float4 b = *reinterpret_cast<const float4*>(xr + idx);
        acc += fabsf(a.x - b.x) + fabsf(a.y - b.y)
             + fabsf(a.z - b.z) + fabsf(a.w - b.w);
    }

    // intra-warp reduce
    #pragma unroll
    for (int o = 16; o > 0; o >>= 1)
        acc += __shfl_xor_sync(0xFFFFFFFFu, acc, o);

    __shared__ float s[8];
    if ((threadIdx.x & 31) == 0) s[threadIdx.x >> 5] = acc;
    __syncthreads();
    if (threadIdx.x < 8) {
        float v = s[threadIdx.x];
        #pragma unroll
        for (int o = 4; o > 0; o >>= 1)
            v += __shfl_xor_sync(0x000000FFu, v, o);
        if (threadIdx.x == 0) g_patch_sum[p] = v;
    }
}

// Single block, 1024 threads = 32 warps; warp w handles frame t=w:
// max over its 256 patch sums (each lane scans 8), then sum of per-t maxes, log.
__global__ __launch_bounds__(1024, 1)
void finalize_kernel(float* __restrict__ out) {
    const int t    = threadIdx.x >> 5;
    const int lane = threadIdx.x & 31;

    float m = 0.0f;  // sums are >= 0, so 0-init also implements the max(.,0) clamp
    #pragma unroll
    for (int i = 0; i < 8; ++i)
        m = fmaxf(m, g_patch_sum[t * 256 + lane * 8 + i]);

    #pragma unroll
    for (int o = 16; o > 0; o >>= 1)
        m = fmaxf(m, __shfl_xor_sync(0xFFFFFFFFu, m, o));

    __shared__ float sm[32];
    if (lane == 0) sm[t] = m;
    __syncthreads();

    if (threadIdx.x < 32) {
        float v = sm[threadIdx.x];
        #pragma unroll
        for (int o = 16; o > 0; o >>= 1)
            v += __shfl_xor_sync(0xFFFFFFFFu, v, o);
        if (threadIdx.x == 0) {
            // patch mean = sum / 6144 ; mean over 32 frames ; log
            *out = logf(v / (32.0f * 6144.0f));
        }
    }
}

extern "C" void kernel_launch(void* const* d_in, const int* in_sizes, int n_in,
                              void* d_out, int out_size) {
    const float* x  = (const float*)d_in[0];
    const float* xr = (const float*)d_in[1];
    float* out = (float*)d_out;

    patch_sum_kernel<<<NPATCH, 256>>>(x, xr);
    finalize_kernel<<<1, 1024>>>(out);
}

// round 5
// speedup vs baseline: 1.0108x; 1.0108x over previous
#include <cuda_runtime.h>
#include <math.h>

// x, x_r : (1, 3, 32, 512, 512) float32
// size=64 -> hc=wc=32 ; 16x16 patches per frame ; t=32
// patch mean = sum(|x - x_r|) / (2*3072) ; out = log(mean_t(max_patches))
// Scaling deferred to the final scalar: log( sum_t(max_p sum|dx|) / (32*6144) )

#define T_DIM 32
#define NPATCH (T_DIM * 16 * 16)        // 8192
#define HW 512
#define TSTRIDE (512u * 512u)
#define CSTRIDE (32u * 512u * 512u)

// Per-frame running max (float bits as int; all values >= 0 so int order == float order).
// Zero-initialized at module load; the finalizing block resets it after each launch,
// so every graph replay starts from 0. The 0-init also implements max(.,0).
__device__ int          g_frame_max[T_DIM];
__device__ unsigned int g_done_count;

__global__ __launch_bounds__(256, 8)
void patch_loss_kernel(const float* __restrict__ x, const float* __restrict__ xr,
                       float* __restrict__ out) {
    const int p  = blockIdx.x;          // t*256 + ph*16 + pw
    const int t  = p >> 8;
    const int ph = (p >> 4) & 15;
    const int pw = p & 15;

    const size_t base = (size_t)t * TSTRIDE + (size_t)ph * 32 * HW + (size_t)pw * 32;

    float acc = 0.0f;
    // 3072 floats/tensor = 768 float4; 256 threads -> 3 units each.
    #pragma unroll
    for (int k = 0; k < 3; ++k) {
        const int e   = threadIdx.x + k * 256;
        const int c   = e >> 8;
        const int rem = e & 255;
        const int row = rem >> 3;
        const int col = (rem & 7) << 2;
        const size_t idx = base + (size_t)c * CSTRIDE + (size_t)row * HW + col;
        const float4 a = *reinterpret_cast<const float4*>(x  + idx);
        const float4 b = *reinterpret_cast<const float4*>(xr + idx);
        acc += fabsf(a.x - b.x) + fabsf(a.y - b.y)
             + fabsf(a.z - b.z) + fabsf(a.w - b.w);
    }

    // intra-warp reduce
    #pragma unroll
    for (int o = 16; o > 0; o >>= 1)
        acc += __shfl_xor_sync(0xFFFFFFFFu, acc, o);

    __shared__ float s[8];
    if ((threadIdx.x & 31) == 0) s[threadIdx.x >> 5] = acc;
    __syncthreads();

    // Warp 0 finishes the block sum, publishes per-frame max, and the last
    // CTA to arrive finalizes the scalar.
    if (threadIdx.x < 32) {
        const int lane = threadIdx.x;
        float v = (lane < 8) ? s[lane] : 0.0f;
        #pragma unroll
        for (int o = 16; o > 0; o >>= 1)
            v += __shfl_xor_sync(0xFFFFFFFFu, v, o);   // lane-uniform total

        unsigned int prev = 0;
        if (lane == 0) {
            atomicMax(&g_frame_max[t], __float_as_int(v));
            __threadfence();                            // publish before ticket
            prev = atomicAdd(&g_done_count, 1u);
        }
        prev = __shfl_sync(0xFFFFFFFFu, prev, 0);

        if (prev == NPATCH - 1) {                       // last block: finalize
            __threadfence();                            // acquire all maxes
            float fm = __int_as_float(__ldcg(&g_frame_max[lane]));  // L2 read, skip L1
            float sum = fm;
            #pragma unroll
            for (int o = 16; o > 0; o >>= 1)
                sum += __shfl_xor_sync(0xFFFFFFFFu, sum, o);
            if (lane == 0) {
                *out = logf(sum / (32.0f * 6144.0f));
                g_done_count = 0u;                      // re-arm for next replay
            }
            __syncwarp();
            g_frame_max[lane] = 0;                      // re-arm maxes (after reads)
        }
    }
}

extern "C" void kernel_launch(void* const* d_in, const int* in_sizes, int n_in,
                              void* d_out, int out_size) {
    const float* x  = (const float*)d_in[0];
    const float* xr = (const float*)d_in[1];
    patch_loss_kernel<<<NPATCH, 256>>>(x, xr, (float*)d_out);
}

// round 6
// speedup vs baseline: 1.0181x; 1.0073x over previous
#include <cuda_runtime.h>
#include <math.h>

// x, x_r : (1, 3, 32, 512, 512) float32
// size=64 -> hc=wc=32 ; 16x16 patches per frame ; t=32
// patch mean = sum(|x - x_r|) / (2*3072) ; out = log(mean_t(max_patches))
// Scaling deferred: out = log( sum_t(max_p sum|dx|) / (32*6144) )

#define T_DIM 32
#define NPATCH (T_DIM * 16 * 16)        // 8192
#define HW 512
#define TSTRIDE (512u * 512u)
#define CSTRIDE (32u * 512u * 512u)

// Per-frame running max as float-bits-in-int (all values >= 0, so int order ==
// float order and the 0-init implements the max(.,0) clamp). Reset by the
// finalizing CTA so every graph replay starts clean.
__device__ int          g_frame_max[T_DIM];
__device__ unsigned int g_done_count;

__device__ __forceinline__ float4 ldcs4(const float* p) {
    float4 v;
    asm volatile("ld.global.cs.v4.f32 {%0,%1,%2,%3}, [%4];"
                 : "=f"(v.x), "=f"(v.y), "=f"(v.z), "=f"(v.w) : "l"(p));
    return v;
}

__global__ __launch_bounds__(256, 8)
void patch_loss_kernel(const float* __restrict__ x, const float* __restrict__ xr,
                       float* __restrict__ out) {
    const int p  = blockIdx.x;          // t*256 + ph*16 + pw
    const int t  = p >> 8;
    const int ph = (p >> 4) & 15;
    const int pw = p & 15;

    const size_t base = (size_t)t * TSTRIDE + (size_t)ph * 32 * HW + (size_t)pw * 32;

    float acc = 0.0f;
    // 3072 floats/tensor = 768 float4; 256 threads -> 3 units each.
    #pragma unroll
    for (int k = 0; k < 3; ++k) {
        const int e   = threadIdx.x + k * 256;
        const int c   = e >> 8;
        const int rem = e & 255;
        const int row = rem >> 3;
        const int col = (rem & 7) << 2;
        const size_t idx = base + (size_t)c * CSTRIDE + (size_t)row * HW + col;
        const float4 a = ldcs4(x  + idx);
        const float4 b = ldcs4(xr + idx);
        acc += fabsf(a.x - b.x) + fabsf(a.y - b.y)
             + fabsf(a.z - b.z) + fabsf(a.w - b.w);
    }

    // intra-warp reduce
    #pragma unroll
    for (int o = 16; o > 0; o >>= 1)
        acc += __shfl_xor_sync(0xFFFFFFFFu, acc, o);

    __shared__ float s[8];
    if ((threadIdx.x & 31) == 0) s[threadIdx.x >> 5] = acc;
    __syncthreads();

    if (threadIdx.x < 32) {
        const int lane = threadIdx.x;
        float v = (lane < 8) ? s[lane] : 0.0f;
        #pragma unroll
        for (int o = 16; o > 0; o >>= 1)
            v += __shfl_xor_sync(0xFFFFFFFFu, v, o);   // lane-uniform block total

        unsigned int prev = 0;
        if (lane == 0) {
            // REDG max (no return) — L2-side, no fence needed before it.
            asm volatile("red.global.max.s32 [%0], %1;"
                         :: "l"(&g_frame_max[t]), "r"(__float_as_int(v)) : "memory");
            // Release-ordered ticket: orders the red above for whoever acquires,
            // WITHOUT a full __threadfence (no L1D flush on the hot path).
            asm volatile("atom.release.gpu.global.add.u32 %0, [%1], 1;"
                         : "=r"(prev) : "l"(&g_done_count) : "memory");
        }
        prev = __shfl_sync(0xFFFFFFFFu, prev, 0);

        if (prev == NPATCH - 1) {                       // last CTA: finalize
            asm volatile("fence.acq_rel.gpu;" ::: "memory");  // single acquire, once
            float sum = __int_as_float(__ldcg(&g_frame_max[lane]));
            #pragma unroll
            for (int o = 16; o > 0; o >>= 1)
                sum += __shfl_xor_sync(0xFFFFFFFFu, sum, o);
            if (lane == 0) {
                *out = logf(sum / (32.0f * 6144.0f));
                g_done_count = 0u;                      // re-arm for next replay
            }
            __syncwarp();
            g_frame_max[lane] = 0;                      // re-arm (after reads)
        }
    }
}

extern "C" void kernel_launch(void* const* d_in, const int* in_sizes, int n_in,
                              void* d_out, int out_size) {
    const float* x  = (const float*)d_in[0];
    const float* xr = (const float*)d_in[1];
    patch_loss_kernel<<<NPATCH, 256>>>(x, xr, (float*)d_out);
}